// round 12
// baseline (speedup 1.0000x reference)
#include <cuda_runtime.h>
#include <cstdint>

// Problem constants
#define SQ 1024
#define HD 768
#define NH 12
#define DH 64
#define NB 8
#define BHCOUNT (NB*NH)   // 96
#define MROWS (NB*SQ)     // 8192
#define ATTN_UNITS (BHCOUNT*8)   // 768

// Scratch (device globals; tf32 bit patterns stored as float)
__device__ float g_q[BHCOUNT*SQ*DH];    // natural head-major tf32, pre-scaled by 0.125
__device__ float g_k[BHCOUNT*SQ*DH];    // natural head-major tf32
__device__ float g_v[BHCOUNT*SQ*DH];    // natural head-major tf32
__device__ float g_ao[MROWS*HD];        // kperm'd tf32 (for O-proj A-path)
__device__ float g_ht[MROWS*HD];        // kperm'd tf32 input h
__device__ float g_wt4[4*HD*HD];        // tf32 weights (natural)
__device__ float g_bm[(size_t)BHCOUNT*SQ*SQ];  // (bias-16)*log2e, FINF if masked; col-permuted
__device__ unsigned int g_ctr;          // persistent-attn work counter

#define LOG2E 1.4426950408889634f
#define MASKED_ARG (-23.08312065422341f)   // (1e-14 - 16) * log2e

// ---------------------------------------------------------------------------
// helpers
// ---------------------------------------------------------------------------
__device__ __forceinline__ uint32_t f2tf(float x) {
    uint32_t r;
    asm("cvt.rna.tf32.f32 %0, %1;" : "=r"(r) : "f"(x));
    return r;
}
__device__ __forceinline__ float f2tff(float x) { return __uint_as_float(f2tf(x)); }
__device__ __forceinline__ float ex2f(float x) {
    float r;
    asm("ex2.approx.ftz.f32 %0, %1;" : "=f"(r) : "f"(x));
    return r;
}
__device__ __forceinline__ int slotf(int c) { return 2*(c&3) + ((c&4)>>2); }

__device__ __forceinline__ void mma8(float* c,
                                     uint32_t a0, uint32_t a1, uint32_t a2, uint32_t a3,
                                     uint32_t b0, uint32_t b1) {
    asm volatile(
        "mma.sync.aligned.m16n8k8.row.col.f32.tf32.tf32.f32 "
        "{%0,%1,%2,%3}, {%4,%5,%6,%7}, {%8,%9}, {%0,%1,%2,%3};"
        : "+f"(c[0]), "+f"(c[1]), "+f"(c[2]), "+f"(c[3])
        : "r"(a0), "r"(a1), "r"(a2), "r"(a3), "r"(b0), "r"(b1));
}

__device__ __forceinline__ uint32_t smem_u32(const void* p) {
    uint32_t a;
    asm("{ .reg .u64 t; cvta.to.shared.u64 t, %1; cvt.u32.u64 %0, t; }"
        : "=r"(a) : "l"(p));
    return a;
}
__device__ __forceinline__ void cpa16(uint32_t dst, const void* src) {
    asm volatile("cp.async.cg.shared.global [%0], [%1], 16;" :: "r"(dst), "l"(src));
}
#define CP_COMMIT() asm volatile("cp.async.commit_group;" ::: "memory")
#define CP_WAIT0()  asm volatile("cp.async.wait_group 0;" ::: "memory")
#define CP_WAIT1()  asm volatile("cp.async.wait_group 1;" ::: "memory")

// ---------------------------------------------------------------------------
// prep: g_ht = kperm'd tf32(h); g_wt4 = tf32(weights); reset attn counter
// ---------------------------------------------------------------------------
__global__ void prep(const float* __restrict__ h,
                     const float* __restrict__ wq, const float* __restrict__ wk,
                     const float* __restrict__ wv, const float* __restrict__ wo)
{
    int i = blockIdx.x * 256 + threadIdx.x;
    if (i == 0) g_ctr = 0u;
    if (i < MROWS*HD) {
        int k = i & 7;
        g_ht[i - k + slotf(k)] = f2tff(h[i]);
    }
    if (i < 4*HD*HD) {
        int z = i / (HD*HD), r = i - z*(HD*HD);
        const float* w = (z == 0) ? wq : (z == 1 ? wk : (z == 2 ? wv : wo));
        g_wt4[i] = f2tff(w[r]);
    }
}

// ---------------------------------------------------------------------------
// GEMM tile body (tf32 mma.sync, cp.async 3-stage).
// ---------------------------------------------------------------------------
#define GA 40
#define GB 132
#define A_ST (128*GA)
#define B_ST (32*GB)
#define STAGE (A_ST + B_ST)
#define NCHUNK (HD/32)
#define NSTAGE 3
#define GEMM_SMEM (NSTAGE*STAGE*4)   // 112128 bytes

__device__ __forceinline__ void gemm_tile(
    float* sm, int bx, int by, int z, int mode,
    const float* __restrict__ bias, float* __restrict__ Cout)
{
    const uint32_t sb = smem_u32(sm);
    const int tid = threadIdx.x;
    const int lane = tid & 31;
    const int wm = (tid >> 5) >> 2, wn = (tid >> 5) & 3;
    const int g = lane >> 2, t = lane & 3;

    const float* A = (mode == 0) ? g_ao : g_ht;
    const float* W = g_wt4 + (size_t)((mode == 0) ? 3 : z) * HD * HD;
    float* C = (mode == 0) ? Cout : (z == 0 ? g_q : (z == 1 ? g_k : g_v));
    const float qs = (mode == 1 && z == 0) ? 0.125f : 1.0f;

    const int m0 = by * 128;
    const int n0 = bx * 128;

    float acc[4][4][4];
#pragma unroll
    for (int i = 0; i < 4; ++i)
#pragma unroll
        for (int j = 0; j < 4; ++j)
#pragma unroll
            for (int r = 0; r < 4; ++r) acc[i][j][r] = 0.0f;

#define G_LOAD(cc, st) do { \
    int k0 = (cc) * 32; \
    uint32_t abase = sb + (uint32_t)((st) * STAGE) * 4; \
    uint32_t bbase = abase + A_ST * 4; \
    _Pragma("unroll") \
    for (int it = 0; it < 4; ++it) { \
        int idx = tid + it * 256; \
        int ar = idx >> 3, ac = idx & 7; \
        cpa16(abase + (uint32_t)(ar * GA + ac * 4) * 4, \
              A + (size_t)(m0 + ar) * HD + k0 + ac * 4); \
        int br = idx >> 5, bc = idx & 31; \
        int sr = (br & ~7) | slotf(br & 7); \
        cpa16(bbase + (uint32_t)(sr * GB + bc * 4) * 4, \
              W + (size_t)(k0 + br) * HD + n0 + bc * 4); \
    } \
    CP_COMMIT(); \
} while (0)

    G_LOAD(0, 0);
    G_LOAD(1, 1);

    int st = 0;
    for (int c = 0; c < NCHUNK; ++c) {
        CP_WAIT1();
        __syncthreads();
        if (c + 2 < NCHUNK) {
            int st2 = st + 2; if (st2 >= NSTAGE) st2 -= NSTAGE;
            G_LOAD(c + 2, st2);
        }

        const float* As = sm + st * STAGE;
        const float* Bs = As + A_ST;
#pragma unroll
        for (int ks = 0; ks < 4; ++ks) {
            float2 ap[4][2];
#pragma unroll
            for (int mf = 0; mf < 4; ++mf) {
                const float* p = As + (wm * 64 + mf * 16 + g) * GA + ks * 8 + 2 * t;
                ap[mf][0] = *(const float2*)p;
                ap[mf][1] = *(const float2*)(p + 8 * GA);
            }
            float bf[4][2];
#pragma unroll
            for (int nf = 0; nf < 4; ++nf) {
                const float* p = Bs + (ks * 8 + 2 * t) * GB + wn * 32 + nf * 8 + g;
                bf[nf][0] = p[0];
                bf[nf][1] = p[GB];
            }
#pragma unroll
            for (int mf = 0; mf < 4; ++mf)
#pragma unroll
                for (int nf = 0; nf < 4; ++nf)
                    mma8(acc[mf][nf],
                         __float_as_uint(ap[mf][0].x), __float_as_uint(ap[mf][1].x),
                         __float_as_uint(ap[mf][0].y), __float_as_uint(ap[mf][1].y),
                         __float_as_uint(bf[nf][0]), __float_as_uint(bf[nf][1]));
        }
        if (++st >= NSTAGE) st = 0;
    }

    // epilogue
#pragma unroll
    for (int mf = 0; mf < 4; ++mf) {
#pragma unroll
        for (int nf = 0; nf < 4; ++nf) {
            int r0 = m0 + wm * 64 + mf * 16 + g;
            int ncol0 = n0 + wn * 32 + nf * 8 + 2 * t;
            float bb0 = bias[ncol0], bb1 = bias[ncol0 + 1];
            float v00 = acc[mf][nf][0] + bb0, v01 = acc[mf][nf][1] + bb1;
            float v10 = acc[mf][nf][2] + bb0, v11 = acc[mf][nf][3] + bb1;
            if (mode == 0) {
                *(float2*)&C[(size_t)r0 * HD + ncol0] = make_float2(v00, v01);
                *(float2*)&C[(size_t)(r0 + 8) * HD + ncol0] = make_float2(v10, v11);
            } else {
                int b = r0 >> 10, sidx = r0 & 1023;
                int hh = ncol0 >> 6, dd = ncol0 & 63;
                size_t base = ((size_t)(b * NH + hh) * SQ + sidx) * DH + dd;
                *(float2*)&C[base] = make_float2(f2tff(v00 * qs), f2tff(v01 * qs));
                *(float2*)&C[base + 8 * DH] = make_float2(f2tff(v10 * qs), f2tff(v11 * qs));
            }
        }
    }
}

// ---------------------------------------------------------------------------
// repack block body: streaming cache hints (evict-first) to avoid polluting
// L2 for the co-resident GEMM tiles.
// ---------------------------------------------------------------------------
__device__ __forceinline__ void repack_block(
    float* sm, int q, int b,
    const float* __restrict__ bias, const int* __restrict__ mask)
{
    float* sbias = sm;                       // SQ*NH floats (48 KB)
    int*   smask = (int*)(sm + SQ * NH);     // SQ ints (4 KB)
    const int tid = threadIdx.x;
    const float FINF = __int_as_float(0x7f800000);

    const float* bsrc = bias + ((size_t)(b * SQ + q) * SQ) * NH;
#pragma unroll
    for (int it = 0; it < 12; ++it) {
        int i4 = (tid + it * 256) * 4;
        *(float4*)&sbias[i4] = __ldcs((const float4*)&bsrc[i4]);
    }
    {
        const int* msrc = mask + (size_t)(b * SQ + q) * SQ;
        int i4 = tid * 4;
        *(int4*)&smask[i4] = __ldcs((const int4*)&msrc[i4]);
    }
    __syncthreads();

#pragma unroll
    for (int h = 0; h < NH; ++h) {
        float* dst = g_bm + (((size_t)(b * NH + h) * SQ + q) * SQ);
        int p0 = tid * 4;
        float o[4];
#pragma unroll
        for (int e = 0; e < 4; ++e) {
            int p = p0 + e;
            int w = p & 63, t = w >> 4, idx = w & 15;
            int k = (p & ~63) + (idx >> 1) * 8 + 2 * t + (idx & 1);
            o[e] = smask[k] ? FINF : (sbias[k * NH + h] - 16.0f) * LOG2E;
        }
        __stcs((float4*)&dst[p0], make_float4(o[0], o[1], o[2], o[3]));
    }
}

// ---------------------------------------------------------------------------
// Fused dispatch: 9344 blocks, 1:8 gemm:repack interleave.
// ---------------------------------------------------------------------------
#define FUSED_BLOCKS (9216 + 128)   // 9344

__global__ __launch_bounds__(256, 2) void fused_qkv_repack(
    const float* __restrict__ bq, const float* __restrict__ bk,
    const float* __restrict__ bv,
    const float* __restrict__ bias, const int* __restrict__ mask)
{
    extern __shared__ float sm[];
    const int gid = blockIdx.x;
    if (((gid & 7) == 0) && (gid < 9216)) {
        int gb = gid >> 3;               // 0..1151
        int z = gb / 384;
        int rem = gb - z * 384;
        int by = rem / 6, bx = rem - by * 6;
        const float* bias_z = (z == 0) ? bq : (z == 1 ? bk : bv);
        gemm_tile(sm, bx, by, z, 1, bias_z, nullptr);
    } else {
        int rix = (gid < 9216) ? (gid - (gid >> 3) - 1) : (gid - 1152);
        int q = rix & 1023, b = rix >> 10;
        repack_block(sm, q, b, bias, mask);
    }
}

// ---------------------------------------------------------------------------
// O-projection GEMM kernel
// ---------------------------------------------------------------------------
__global__ __launch_bounds__(256, 2) void gemm_o(
    const float* __restrict__ bo, float* __restrict__ Cout)
{
    extern __shared__ float sm[];
    gemm_tile(sm, blockIdx.x, blockIdx.y, 0, 0, bo, Cout);
}

// ---------------------------------------------------------------------------
// Flash attention — persistent CTAs with atomic work queue; __ldcs bm reads.
// smem floats: K[2][64][68], V[2][64][72], Ps[128][68] (Q staging + P).
// ---------------------------------------------------------------------------
#define KSTR 68
#define VSTR 72
#define K_OFF(s)  ((s)*64*KSTR)
#define V_OFF(s)  (2*64*KSTR + (s)*64*VSTR)
#define P_OFF     (2*64*KSTR + 2*64*VSTR)
#define ATTN_FLOATS (P_OFF + 128*KSTR)
#define ATTN_SMEM (ATTN_FLOATS*4)   // 106496 bytes

__global__ __launch_bounds__(256, 2) void attn_kernel()
{
    extern __shared__ float sm[];
    __shared__ int s_unit;
    const uint32_t sb = smem_u32(sm);
    const float FINF = __int_as_float(0x7f800000);
    float* Ps = sm + P_OFF;

    const int tid = threadIdx.x;
    const int wid = tid >> 5, lane = tid & 31;
    const int g = lane >> 2, t = lane & 3;
    const int rl = wid * 16 + g;

    for (;;) {
        if (tid == 0) s_unit = (int)atomicAdd(&g_ctr, 1u);
        __syncthreads();
        const int unit = s_unit;
        __syncthreads();
        if (unit >= ATTN_UNITS) break;

        const int bh = unit >> 3;
        const int b = bh / NH, hh = bh - b * NH;
        const int q0 = (unit & 7) * 128;

        const float* qg = g_q + ((size_t)bh * SQ + q0) * DH;
        const float* kg = g_k + (size_t)bh * SQ * DH;
        const float* vg = g_v + (size_t)bh * SQ * DH;

        // issue chunk-0 K/V cp.async first (overlaps Q staging)
#pragma unroll
        for (int it = 0; it < 4; ++it) {
            int idx = tid + it * 256;
            int row = idx >> 4, c4 = idx & 15;
            cpa16(sb + (uint32_t)(K_OFF(0) + row * KSTR + c4 * 4) * 4,
                  kg + (size_t)row * 64 + c4 * 4);
            cpa16(sb + (uint32_t)(V_OFF(0) + row * VSTR + c4 * 4) * 4,
                  vg + (size_t)row * 64 + c4 * 4);
        }
        CP_COMMIT();

        // stage Q tile into Ps, then extract fragments to registers
#pragma unroll
        for (int it = 0; it < 8; ++it) {
            int idx = tid + it * 256;
            int row = idx >> 4, c4 = idx & 15;
            *(float4*)&Ps[row * KSTR + c4 * 4] =
                *(const float4*)&qg[(size_t)row * 64 + c4 * 4];
        }
        __syncthreads();
        uint32_t qf[8][4];
#pragma unroll
        for (int ks = 0; ks < 8; ++ks) {
            qf[ks][0] = __float_as_uint(Ps[rl * KSTR + ks * 8 + t]);
            qf[ks][1] = __float_as_uint(Ps[(rl + 8) * KSTR + ks * 8 + t]);
            qf[ks][2] = __float_as_uint(Ps[rl * KSTR + ks * 8 + t + 4]);
            qf[ks][3] = __float_as_uint(Ps[(rl + 8) * KSTR + ks * 8 + t + 4]);
        }
        CP_WAIT0();
        __syncthreads();

        const int r0 = q0 + rl;
        const int r1 = r0 + 8;
        const float* bm_r0 = g_bm + ((size_t)bh * SQ + r0) * SQ;
        const float* bm_r1 = g_bm + ((size_t)bh * SQ + r1) * SQ;

        float l0 = 0.0f, l1 = 0.0f;
        float oacc[8][4];
#pragma unroll
        for (int nf = 0; nf < 8; ++nf)
#pragma unroll
            for (int r = 0; r < 4; ++r) oacc[nf][r] = 0.0f;

        for (int kb = 0; kb < SQ / 64; ++kb) {
            const int s = kb & 1;
            const int k0 = kb * 64;

            // ---- cp.async next K/V chunk ----
            if (kb + 1 < SQ / 64) {
                const int kn = k0 + 64;
#pragma unroll
                for (int it = 0; it < 4; ++it) {
                    int idx = tid + it * 256;
                    int row = idx >> 4, c4 = idx & 15;
                    cpa16(sb + (uint32_t)(K_OFF(s ^ 1) + row * KSTR + c4 * 4) * 4,
                          kg + (size_t)(kn + row) * 64 + c4 * 4);
                    cpa16(sb + (uint32_t)(V_OFF(s ^ 1) + row * VSTR + c4 * 4) * 4,
                          vg + (size_t)(kn + row) * 64 + c4 * 4);
                }
                CP_COMMIT();
            }

            // ---- S = Q K^T (sacc = qk * 0.125, Q pre-scaled) ----
            const float* Ksf = sm + K_OFF(s);
            float sacc[8][4];
#pragma unroll
            for (int nf = 0; nf < 8; ++nf)
#pragma unroll
                for (int r = 0; r < 4; ++r) sacc[nf][r] = 0.0f;
#pragma unroll
            for (int ks = 0; ks < 8; ++ks) {
#pragma unroll
                for (int nf = 0; nf < 8; ++nf) {
                    const float* kp = Ksf + (nf * 8 + g) * KSTR + ks * 8 + t;
                    mma8(sacc[nf], qf[ks][0], qf[ks][1], qf[ks][2], qf[ks][3],
                         __float_as_uint(kp[0]), __float_as_uint(kp[4]));
                }
            }

            // ---- fold: arg = sacc*log2e + bm (streaming loads); ex2 ----
            float rs0 = 0.0f, rs1 = 0.0f;
#pragma unroll
            for (int v = 0; v < 4; ++v) {
                int base = k0 + t * 16 + v * 4;
                float4 U = __ldcs((const float4*)&bm_r0[base]);
                float4 Wv4 = __ldcs((const float4*)&bm_r1[base]);
                {
                    int nf = 2 * v;
                    float a0 = (U.x == FINF)   ? MASKED_ARG : fmaf(sacc[nf][0], LOG2E, U.x);
                    float a1 = (U.y == FINF)   ? MASKED_ARG : fmaf(sacc[nf][1], LOG2E, U.y);
                    float a2 = (Wv4.x == FINF) ? MASKED_ARG : fmaf(sacc[nf][2], LOG2E, Wv4.x);
                    float a3 = (Wv4.y == FINF) ? MASKED_ARG : fmaf(sacc[nf][3], LOG2E, Wv4.y);
                    sacc[nf][0] = ex2f(a0); sacc[nf][1] = ex2f(a1);
                    sacc[nf][2] = ex2f(a2); sacc[nf][3] = ex2f(a3);
                    rs0 += sacc[nf][0] + sacc[nf][1];
                    rs1 += sacc[nf][2] + sacc[nf][3];
                }
                {
                    int nf = 2 * v + 1;
                    float a0 = (U.z == FINF)   ? MASKED_ARG : fmaf(sacc[nf][0], LOG2E, U.z);
                    float a1 = (U.w == FINF)   ? MASKED_ARG : fmaf(sacc[nf][1], LOG2E, U.w);
                    float a2 = (Wv4.z == FINF) ? MASKED_ARG : fmaf(sacc[nf][2], LOG2E, Wv4.z);
                    float a3 = (Wv4.w == FINF) ? MASKED_ARG : fmaf(sacc[nf][3], LOG2E, Wv4.w);
                    sacc[nf][0] = ex2f(a0); sacc[nf][1] = ex2f(a1);
                    sacc[nf][2] = ex2f(a2); sacc[nf][3] = ex2f(a3);
                    rs0 += sacc[nf][0] + sacc[nf][1];
                    rs1 += sacc[nf][2] + sacc[nf][3];
                }
            }
            l0 += rs0;
            l1 += rs1;

            // ---- P (tf32 bits) -> smem, warp-local rows ----
#pragma unroll
            for (int nf = 0; nf < 8; ++nf) {
                int kc = nf * 8 + 2 * t;
                *(float2*)&Ps[rl * KSTR + kc] =
                    make_float2(f2tff(sacc[nf][0]), f2tff(sacc[nf][1]));
                *(float2*)&Ps[(rl + 8) * KSTR + kc] =
                    make_float2(f2tff(sacc[nf][2]), f2tff(sacc[nf][3]));
            }
            __syncwarp();

            // ---- O += P V ----
            const float* Vsf = sm + V_OFF(s);
#pragma unroll
            for (int ks = 0; ks < 8; ++ks) {
                const float* pp = Ps + rl * KSTR + ks * 8 + t;
                uint32_t a0 = __float_as_uint(pp[0]);
                uint32_t a1 = __float_as_uint(pp[8 * KSTR]);
                uint32_t a2 = __float_as_uint(pp[4]);
                uint32_t a3 = __float_as_uint(pp[8 * KSTR + 4]);
#pragma unroll
                for (int nf = 0; nf < 8; ++nf) {
                    const float* vp = Vsf + (ks * 8 + t) * VSTR + nf * 8 + g;
                    mma8(oacc[nf], a0, a1, a2, a3,
                         __float_as_uint(vp[0]), __float_as_uint(vp[4 * VSTR]));
                }
            }

            if (kb + 1 < SQ / 64) CP_WAIT0();
            __syncthreads();
        }

        // ---- final l reduction + normalize + write g_ao (kperm tf32) ----
        l0 += __shfl_xor_sync(0xffffffffu, l0, 1);
        l0 += __shfl_xor_sync(0xffffffffu, l0, 2);
        l1 += __shfl_xor_sync(0xffffffffu, l1, 1);
        l1 += __shfl_xor_sync(0xffffffffu, l1, 2);
        float inv0 = 1.0f / l0, inv1 = 1.0f / l1;
        int s0 = slotf(2 * t), s1 = slotf(2 * t + 1);
#pragma unroll
        for (int nf = 0; nf < 8; ++nf) {
            int colbase = hh * 64 + nf * 8;
            size_t b0 = (size_t)(b * SQ + r0) * HD + colbase;
            size_t b1 = (size_t)(b * SQ + r1) * HD + colbase;
            g_ao[b0 + s0] = f2tff(oacc[nf][0] * inv0);
            g_ao[b0 + s1] = f2tff(oacc[nf][1] * inv0);
            g_ao[b1 + s0] = f2tff(oacc[nf][2] * inv1);
            g_ao[b1 + s1] = f2tff(oacc[nf][3] * inv1);
        }
        __syncthreads();   // smem reuse safety before next unit
    }
}

// ---------------------------------------------------------------------------
extern "C" void kernel_launch(void* const* d_in, const int* in_sizes, int n_in,
                              void* d_out, int out_size)
{
    const float* h  = (const float*)d_in[0];
    const float* ab = (const float*)d_in[1];
    const int*   mk = (const int*)d_in[2];
    const float* Wq = (const float*)d_in[3];
    const float* bq = (const float*)d_in[4];
    const float* Wk = (const float*)d_in[5];
    const float* bk = (const float*)d_in[6];
    const float* Wv = (const float*)d_in[7];
    const float* bv = (const float*)d_in[8];
    const float* Wo = (const float*)d_in[9];
    const float* bo = (const float*)d_in[10];
    float* out = (float*)d_out;

    cudaFuncSetAttribute(fused_qkv_repack,
                         cudaFuncAttributeMaxDynamicSharedMemorySize, GEMM_SMEM);
    cudaFuncSetAttribute(gemm_o,
                         cudaFuncAttributeMaxDynamicSharedMemorySize, GEMM_SMEM);
    cudaFuncSetAttribute(attn_kernel,
                         cudaFuncAttributeMaxDynamicSharedMemorySize, ATTN_SMEM);

    int nsm = 148;
    cudaDeviceGetAttribute(&nsm, cudaDevAttrMultiProcessorCount, 0);
    int attn_blocks = 2 * nsm;
    if (attn_blocks > ATTN_UNITS) attn_blocks = ATTN_UNITS;

    prep<<<(MROWS*HD + 255) / 256, 256>>>(h, Wq, Wk, Wv, Wo);
    fused_qkv_repack<<<FUSED_BLOCKS, 256, GEMM_SMEM>>>(bq, bk, bv, ab, mk);
    attn_kernel<<<attn_blocks, 256, ATTN_SMEM>>>();
    gemm_o<<<dim3(HD / 128, MROWS / 128), 256, GEMM_SMEM>>>(bo, out);
}

// round 13
// speedup vs baseline: 1.0425x; 1.0425x over previous
#include <cuda_runtime.h>
#include <cstdint>

// Problem constants
#define SQ 1024
#define HD 768
#define NH 12
#define DH 64
#define NB 8
#define BHCOUNT (NB*NH)   // 96
#define MROWS (NB*SQ)     // 8192

// Scratch (device globals; tf32 bit patterns stored as float)
__device__ float g_q[BHCOUNT*SQ*DH];    // natural head-major tf32, pre-scaled by 0.125
__device__ float g_k[BHCOUNT*SQ*DH];    // natural head-major tf32
__device__ float g_v[BHCOUNT*SQ*DH];    // natural head-major tf32
__device__ float g_ao[MROWS*HD];        // kperm'd tf32 (for O-proj A-path)
__device__ float g_ht[MROWS*HD];        // kperm'd tf32 input h
__device__ float g_wt4[4*HD*HD];        // tf32 weights (natural)
__device__ float g_bm[(size_t)BHCOUNT*SQ*SQ];  // (bias-16)*log2e, FINF if masked; col-permuted

#define LOG2E 1.4426950408889634f
#define MASKED_ARG (-23.08312065422341f)   // (1e-14 - 16) * log2e

// ---------------------------------------------------------------------------
// helpers
// ---------------------------------------------------------------------------
__device__ __forceinline__ uint32_t f2tf(float x) {
    uint32_t r;
    asm("cvt.rna.tf32.f32 %0, %1;" : "=r"(r) : "f"(x));
    return r;
}
__device__ __forceinline__ float f2tff(float x) { return __uint_as_float(f2tf(x)); }
__device__ __forceinline__ float ex2f(float x) {
    float r;
    asm("ex2.approx.ftz.f32 %0, %1;" : "=f"(r) : "f"(x));
    return r;
}
__device__ __forceinline__ int slotf(int c) { return 2*(c&3) + ((c&4)>>2); }

__device__ __forceinline__ void mma8(float* c,
                                     uint32_t a0, uint32_t a1, uint32_t a2, uint32_t a3,
                                     uint32_t b0, uint32_t b1) {
    asm volatile(
        "mma.sync.aligned.m16n8k8.row.col.f32.tf32.tf32.f32 "
        "{%0,%1,%2,%3}, {%4,%5,%6,%7}, {%8,%9}, {%0,%1,%2,%3};"
        : "+f"(c[0]), "+f"(c[1]), "+f"(c[2]), "+f"(c[3])
        : "r"(a0), "r"(a1), "r"(a2), "r"(a3), "r"(b0), "r"(b1));
}

__device__ __forceinline__ uint32_t smem_u32(const void* p) {
    uint32_t a;
    asm("{ .reg .u64 t; cvta.to.shared.u64 t, %1; cvt.u32.u64 %0, t; }"
        : "=r"(a) : "l"(p));
    return a;
}
__device__ __forceinline__ void cpa16(uint32_t dst, const void* src) {
    asm volatile("cp.async.cg.shared.global [%0], [%1], 16;" :: "r"(dst), "l"(src));
}
#define CP_COMMIT() asm volatile("cp.async.commit_group;" ::: "memory")
#define CP_WAIT0()  asm volatile("cp.async.wait_group 0;" ::: "memory")
#define CP_WAIT1()  asm volatile("cp.async.wait_group 1;" ::: "memory")

// ---------------------------------------------------------------------------
// prep: g_ht = kperm'd tf32(h); g_wt4 = tf32(weights), natural
// ---------------------------------------------------------------------------
__global__ void prep(const float* __restrict__ h,
                     const float* __restrict__ wq, const float* __restrict__ wk,
                     const float* __restrict__ wv, const float* __restrict__ wo)
{
    int i = blockIdx.x * 256 + threadIdx.x;
    if (i < MROWS*HD) {
        int k = i & 7;
        g_ht[i - k + slotf(k)] = f2tff(h[i]);
    }
    if (i < 4*HD*HD) {
        int z = i / (HD*HD), r = i - z*(HD*HD);
        const float* w = (z == 0) ? wq : (z == 1 ? wk : (z == 2 ? wv : wo));
        g_wt4[i] = f2tff(w[r]);
    }
}

// ---------------------------------------------------------------------------
// GEMM tile body (tf32 mma.sync, cp.async 3-stage).
// ---------------------------------------------------------------------------
#define GA 40
#define GB 132
#define A_ST (128*GA)
#define B_ST (32*GB)
#define STAGE (A_ST + B_ST)
#define NCHUNK (HD/32)
#define NSTAGE 3
#define GEMM_SMEM (NSTAGE*STAGE*4)   // 112128 bytes

__device__ __forceinline__ void gemm_tile(
    float* sm, int bx, int by, int z, int mode,
    const float* __restrict__ bias, float* __restrict__ Cout)
{
    const uint32_t sb = smem_u32(sm);
    const int tid = threadIdx.x;
    const int lane = tid & 31;
    const int wm = (tid >> 5) >> 2, wn = (tid >> 5) & 3;
    const int g = lane >> 2, t = lane & 3;

    const float* A = (mode == 0) ? g_ao : g_ht;
    const float* W = g_wt4 + (size_t)((mode == 0) ? 3 : z) * HD * HD;
    float* C = (mode == 0) ? Cout : (z == 0 ? g_q : (z == 1 ? g_k : g_v));
    const float qs = (mode == 1 && z == 0) ? 0.125f : 1.0f;

    const int m0 = by * 128;
    const int n0 = bx * 128;

    float acc[4][4][4];
#pragma unroll
    for (int i = 0; i < 4; ++i)
#pragma unroll
        for (int j = 0; j < 4; ++j)
#pragma unroll
            for (int r = 0; r < 4; ++r) acc[i][j][r] = 0.0f;

#define G_LOAD(cc, st) do { \
    int k0 = (cc) * 32; \
    uint32_t abase = sb + (uint32_t)((st) * STAGE) * 4; \
    uint32_t bbase = abase + A_ST * 4; \
    _Pragma("unroll") \
    for (int it = 0; it < 4; ++it) { \
        int idx = tid + it * 256; \
        int ar = idx >> 3, ac = idx & 7; \
        cpa16(abase + (uint32_t)(ar * GA + ac * 4) * 4, \
              A + (size_t)(m0 + ar) * HD + k0 + ac * 4); \
        int br = idx >> 5, bc = idx & 31; \
        int sr = (br & ~7) | slotf(br & 7); \
        cpa16(bbase + (uint32_t)(sr * GB + bc * 4) * 4, \
              W + (size_t)(k0 + br) * HD + n0 + bc * 4); \
    } \
    CP_COMMIT(); \
} while (0)

    G_LOAD(0, 0);
    G_LOAD(1, 1);

    int st = 0;
    for (int c = 0; c < NCHUNK; ++c) {
        CP_WAIT1();
        __syncthreads();
        if (c + 2 < NCHUNK) {
            int st2 = st + 2; if (st2 >= NSTAGE) st2 -= NSTAGE;
            G_LOAD(c + 2, st2);
        }

        const float* As = sm + st * STAGE;
        const float* Bs = As + A_ST;
#pragma unroll
        for (int ks = 0; ks < 4; ++ks) {
            float2 ap[4][2];
#pragma unroll
            for (int mf = 0; mf < 4; ++mf) {
                const float* p = As + (wm * 64 + mf * 16 + g) * GA + ks * 8 + 2 * t;
                ap[mf][0] = *(const float2*)p;
                ap[mf][1] = *(const float2*)(p + 8 * GA);
            }
            float bf[4][2];
#pragma unroll
            for (int nf = 0; nf < 4; ++nf) {
                const float* p = Bs + (ks * 8 + 2 * t) * GB + wn * 32 + nf * 8 + g;
                bf[nf][0] = p[0];
                bf[nf][1] = p[GB];
            }
#pragma unroll
            for (int mf = 0; mf < 4; ++mf)
#pragma unroll
                for (int nf = 0; nf < 4; ++nf)
                    mma8(acc[mf][nf],
                         __float_as_uint(ap[mf][0].x), __float_as_uint(ap[mf][1].x),
                         __float_as_uint(ap[mf][0].y), __float_as_uint(ap[mf][1].y),
                         __float_as_uint(bf[nf][0]), __float_as_uint(bf[nf][1]));
        }
        if (++st >= NSTAGE) st = 0;
    }

    // epilogue
#pragma unroll
    for (int mf = 0; mf < 4; ++mf) {
#pragma unroll
        for (int nf = 0; nf < 4; ++nf) {
            int r0 = m0 + wm * 64 + mf * 16 + g;
            int ncol0 = n0 + wn * 32 + nf * 8 + 2 * t;
            float bb0 = bias[ncol0], bb1 = bias[ncol0 + 1];
            float v00 = acc[mf][nf][0] + bb0, v01 = acc[mf][nf][1] + bb1;
            float v10 = acc[mf][nf][2] + bb0, v11 = acc[mf][nf][3] + bb1;
            if (mode == 0) {
                *(float2*)&C[(size_t)r0 * HD + ncol0] = make_float2(v00, v01);
                *(float2*)&C[(size_t)(r0 + 8) * HD + ncol0] = make_float2(v10, v11);
            } else {
                int b = r0 >> 10, sidx = r0 & 1023;
                int hh = ncol0 >> 6, dd = ncol0 & 63;
                size_t base = ((size_t)(b * NH + hh) * SQ + sidx) * DH + dd;
                *(float2*)&C[base] = make_float2(f2tff(v00 * qs), f2tff(v01 * qs));
                *(float2*)&C[base + 8 * DH] = make_float2(f2tff(v10 * qs), f2tff(v11 * qs));
            }
        }
    }
}

// ---------------------------------------------------------------------------
// repack block body: streaming cache hints (evict-first) so the 800 MB bias
// stream doesn't evict the co-resident GEMM CTAs' W tiles from L2.
// ---------------------------------------------------------------------------
__device__ __forceinline__ void repack_block(
    float* sm, int q, int b,
    const float* __restrict__ bias, const int* __restrict__ mask)
{
    float* sbias = sm;                       // SQ*NH floats (48 KB)
    int*   smask = (int*)(sm + SQ * NH);     // SQ ints (4 KB)
    const int tid = threadIdx.x;
    const float FINF = __int_as_float(0x7f800000);

    const float* bsrc = bias + ((size_t)(b * SQ + q) * SQ) * NH;
#pragma unroll
    for (int it = 0; it < 12; ++it) {
        int i4 = (tid + it * 256) * 4;
        *(float4*)&sbias[i4] = __ldcs((const float4*)&bsrc[i4]);
    }
    {
        const int* msrc = mask + (size_t)(b * SQ + q) * SQ;
        int i4 = tid * 4;
        *(int4*)&smask[i4] = __ldcs((const int4*)&msrc[i4]);
    }
    __syncthreads();

#pragma unroll
    for (int h = 0; h < NH; ++h) {
        float* dst = g_bm + (((size_t)(b * NH + h) * SQ + q) * SQ);
        int p0 = tid * 4;
        float o[4];
#pragma unroll
        for (int e = 0; e < 4; ++e) {
            int p = p0 + e;
            int w = p & 63, t = w >> 4, idx = w & 15;
            int k = (p & ~63) + (idx >> 1) * 8 + 2 * t + (idx & 1);
            o[e] = smask[k] ? FINF : (sbias[k * NH + h] - 16.0f) * LOG2E;
        }
        __stcs((float4*)&dst[p0], make_float4(o[0], o[1], o[2], o[3]));
    }
}

// ---------------------------------------------------------------------------
// Fused dispatch: 9344 blocks, 1:8 gemm:repack interleave.
// ---------------------------------------------------------------------------
#define FUSED_BLOCKS (9216 + 128)   // 9344

__global__ __launch_bounds__(256, 2) void fused_qkv_repack(
    const float* __restrict__ bq, const float* __restrict__ bk,
    const float* __restrict__ bv,
    const float* __restrict__ bias, const int* __restrict__ mask)
{
    extern __shared__ float sm[];
    const int gid = blockIdx.x;
    if (((gid & 7) == 0) && (gid < 9216)) {
        int gb = gid >> 3;               // 0..1151
        int z = gb / 384;
        int rem = gb - z * 384;
        int by = rem / 6, bx = rem - by * 6;
        const float* bias_z = (z == 0) ? bq : (z == 1 ? bk : bv);
        gemm_tile(sm, bx, by, z, 1, bias_z, nullptr);
    } else {
        int rix = (gid < 9216) ? (gid - (gid >> 3) - 1) : (gid - 1152);
        int q = rix & 1023, b = rix >> 10;
        repack_block(sm, q, b, bias, mask);
    }
}

// ---------------------------------------------------------------------------
// O-projection GEMM kernel
// ---------------------------------------------------------------------------
__global__ __launch_bounds__(256, 2) void gemm_o(
    const float* __restrict__ bo, float* __restrict__ Cout)
{
    extern __shared__ float sm[];
    gemm_tile(sm, blockIdx.x, blockIdx.y, 0, 0, bo, Cout);
}

// ---------------------------------------------------------------------------
// Flash attention — R11 winner, unchanged (grid launch, normal loads).
// smem floats: K[2][64][68], V[2][64][72], Ps[128][68] (Q staging + P).
// ---------------------------------------------------------------------------
#define KSTR 68
#define VSTR 72
#define K_OFF(s)  ((s)*64*KSTR)
#define V_OFF(s)  (2*64*KSTR + (s)*64*VSTR)
#define P_OFF     (2*64*KSTR + 2*64*VSTR)
#define ATTN_FLOATS (P_OFF + 128*KSTR)
#define ATTN_SMEM (ATTN_FLOATS*4)   // 106496 bytes

__global__ __launch_bounds__(256, 2) void attn_kernel()
{
    extern __shared__ float sm[];
    const uint32_t sb = smem_u32(sm);
    const float FINF = __int_as_float(0x7f800000);
    float* Ps = sm + P_OFF;

    const int bh = blockIdx.y;
    const int b = bh / NH, hh = bh - b * NH;
    const int q0 = blockIdx.x * 128;
    const int tid = threadIdx.x;
    const int wid = tid >> 5, lane = tid & 31;
    const int g = lane >> 2, t = lane & 3;
    const int rl = wid * 16 + g;

    const float* qg = g_q + ((size_t)bh * SQ + q0) * DH;
    const float* kg = g_k + (size_t)bh * SQ * DH;
    const float* vg = g_v + (size_t)bh * SQ * DH;

    // issue chunk-0 K/V cp.async first (overlaps Q staging)
#pragma unroll
    for (int it = 0; it < 4; ++it) {
        int idx = tid + it * 256;
        int row = idx >> 4, c4 = idx & 15;
        cpa16(sb + (uint32_t)(K_OFF(0) + row * KSTR + c4 * 4) * 4,
              kg + (size_t)row * 64 + c4 * 4);
        cpa16(sb + (uint32_t)(V_OFF(0) + row * VSTR + c4 * 4) * 4,
              vg + (size_t)row * 64 + c4 * 4);
    }
    CP_COMMIT();

    // stage Q tile (128x64) into Ps, then extract fragments to registers
#pragma unroll
    for (int it = 0; it < 8; ++it) {
        int idx = tid + it * 256;
        int row = idx >> 4, c4 = idx & 15;
        *(float4*)&Ps[row * KSTR + c4 * 4] = *(const float4*)&qg[(size_t)row * 64 + c4 * 4];
    }
    __syncthreads();
    uint32_t qf[8][4];
#pragma unroll
    for (int ks = 0; ks < 8; ++ks) {
        qf[ks][0] = __float_as_uint(Ps[rl * KSTR + ks * 8 + t]);
        qf[ks][1] = __float_as_uint(Ps[(rl + 8) * KSTR + ks * 8 + t]);
        qf[ks][2] = __float_as_uint(Ps[rl * KSTR + ks * 8 + t + 4]);
        qf[ks][3] = __float_as_uint(Ps[(rl + 8) * KSTR + ks * 8 + t + 4]);
    }
    CP_WAIT0();
    __syncthreads();

    const int r0 = q0 + rl;
    const int r1 = r0 + 8;
    const float* bm_r0 = g_bm + ((size_t)bh * SQ + r0) * SQ;
    const float* bm_r1 = g_bm + ((size_t)bh * SQ + r1) * SQ;

    float l0 = 0.0f, l1 = 0.0f;
    float oacc[8][4];
#pragma unroll
    for (int nf = 0; nf < 8; ++nf)
#pragma unroll
        for (int r = 0; r < 4; ++r) oacc[nf][r] = 0.0f;

    for (int kb = 0; kb < SQ / 64; ++kb) {
        const int s = kb & 1;
        const int k0 = kb * 64;

        // ---- cp.async next K/V chunk ----
        if (kb + 1 < SQ / 64) {
            const int kn = k0 + 64;
#pragma unroll
            for (int it = 0; it < 4; ++it) {
                int idx = tid + it * 256;
                int row = idx >> 4, c4 = idx & 15;
                cpa16(sb + (uint32_t)(K_OFF(s ^ 1) + row * KSTR + c4 * 4) * 4,
                      kg + (size_t)(kn + row) * 64 + c4 * 4);
                cpa16(sb + (uint32_t)(V_OFF(s ^ 1) + row * VSTR + c4 * 4) * 4,
                      vg + (size_t)(kn + row) * 64 + c4 * 4);
            }
            CP_COMMIT();
        }

        // ---- S = Q K^T (sacc = qk * 0.125, Q pre-scaled) ----
        const float* Ksf = sm + K_OFF(s);
        float sacc[8][4];
#pragma unroll
        for (int nf = 0; nf < 8; ++nf)
#pragma unroll
            for (int r = 0; r < 4; ++r) sacc[nf][r] = 0.0f;
#pragma unroll
        for (int ks = 0; ks < 8; ++ks) {
#pragma unroll
            for (int nf = 0; nf < 8; ++nf) {
                const float* kp = Ksf + (nf * 8 + g) * KSTR + ks * 8 + t;
                mma8(sacc[nf], qf[ks][0], qf[ks][1], qf[ks][2], qf[ks][3],
                     __float_as_uint(kp[0]), __float_as_uint(kp[4]));
            }
        }

        // ---- fold: arg = sacc*log2e + bm (bm pre-scaled); ex2 ----
        float rs0 = 0.0f, rs1 = 0.0f;
#pragma unroll
        for (int v = 0; v < 4; ++v) {
            int base = k0 + t * 16 + v * 4;
            float4 U = *(const float4*)&bm_r0[base];
            float4 Wv4 = *(const float4*)&bm_r1[base];
            {
                int nf = 2 * v;
                float a0 = (U.x == FINF)   ? MASKED_ARG : fmaf(sacc[nf][0], LOG2E, U.x);
                float a1 = (U.y == FINF)   ? MASKED_ARG : fmaf(sacc[nf][1], LOG2E, U.y);
                float a2 = (Wv4.x == FINF) ? MASKED_ARG : fmaf(sacc[nf][2], LOG2E, Wv4.x);
                float a3 = (Wv4.y == FINF) ? MASKED_ARG : fmaf(sacc[nf][3], LOG2E, Wv4.y);
                sacc[nf][0] = ex2f(a0); sacc[nf][1] = ex2f(a1);
                sacc[nf][2] = ex2f(a2); sacc[nf][3] = ex2f(a3);
                rs0 += sacc[nf][0] + sacc[nf][1];
                rs1 += sacc[nf][2] + sacc[nf][3];
            }
            {
                int nf = 2 * v + 1;
                float a0 = (U.z == FINF)   ? MASKED_ARG : fmaf(sacc[nf][0], LOG2E, U.z);
                float a1 = (U.w == FINF)   ? MASKED_ARG : fmaf(sacc[nf][1], LOG2E, U.w);
                float a2 = (Wv4.z == FINF) ? MASKED_ARG : fmaf(sacc[nf][2], LOG2E, Wv4.z);
                float a3 = (Wv4.w == FINF) ? MASKED_ARG : fmaf(sacc[nf][3], LOG2E, Wv4.w);
                sacc[nf][0] = ex2f(a0); sacc[nf][1] = ex2f(a1);
                sacc[nf][2] = ex2f(a2); sacc[nf][3] = ex2f(a3);
                rs0 += sacc[nf][0] + sacc[nf][1];
                rs1 += sacc[nf][2] + sacc[nf][3];
            }
        }
        l0 += rs0;
        l1 += rs1;

        // ---- P (tf32 bits) -> smem, warp-local rows ----
#pragma unroll
        for (int nf = 0; nf < 8; ++nf) {
            int kc = nf * 8 + 2 * t;
            *(float2*)&Ps[rl * KSTR + kc] =
                make_float2(f2tff(sacc[nf][0]), f2tff(sacc[nf][1]));
            *(float2*)&Ps[(rl + 8) * KSTR + kc] =
                make_float2(f2tff(sacc[nf][2]), f2tff(sacc[nf][3]));
        }
        __syncwarp();

        // ---- O += P V ----
        const float* Vsf = sm + V_OFF(s);
#pragma unroll
        for (int ks = 0; ks < 8; ++ks) {
            const float* pp = Ps + rl * KSTR + ks * 8 + t;
            uint32_t a0 = __float_as_uint(pp[0]);
            uint32_t a1 = __float_as_uint(pp[8 * KSTR]);
            uint32_t a2 = __float_as_uint(pp[4]);
            uint32_t a3 = __float_as_uint(pp[8 * KSTR + 4]);
#pragma unroll
            for (int nf = 0; nf < 8; ++nf) {
                const float* vp = Vsf + (ks * 8 + t) * VSTR + nf * 8 + g;
                mma8(oacc[nf], a0, a1, a2, a3,
                     __float_as_uint(vp[0]), __float_as_uint(vp[4 * VSTR]));
            }
        }

        if (kb + 1 < SQ / 64) CP_WAIT0();
        __syncthreads();
    }

    // ---- final l reduction (quad) + normalize + write g_ao (kperm tf32) ----
    l0 += __shfl_xor_sync(0xffffffffu, l0, 1);
    l0 += __shfl_xor_sync(0xffffffffu, l0, 2);
    l1 += __shfl_xor_sync(0xffffffffu, l1, 1);
    l1 += __shfl_xor_sync(0xffffffffu, l1, 2);
    float inv0 = 1.0f / l0, inv1 = 1.0f / l1;
    int s0 = slotf(2 * t), s1 = slotf(2 * t + 1);
#pragma unroll
    for (int nf = 0; nf < 8; ++nf) {
        int colbase = hh * 64 + nf * 8;
        size_t b0 = (size_t)(b * SQ + r0) * HD + colbase;
        size_t b1 = (size_t)(b * SQ + r1) * HD + colbase;
        g_ao[b0 + s0] = f2tff(oacc[nf][0] * inv0);
        g_ao[b0 + s1] = f2tff(oacc[nf][1] * inv0);
        g_ao[b1 + s0] = f2tff(oacc[nf][2] * inv1);
        g_ao[b1 + s1] = f2tff(oacc[nf][3] * inv1);
    }
}

// ---------------------------------------------------------------------------
extern "C" void kernel_launch(void* const* d_in, const int* in_sizes, int n_in,
                              void* d_out, int out_size)
{
    const float* h  = (const float*)d_in[0];
    const float* ab = (const float*)d_in[1];
    const int*   mk = (const int*)d_in[2];
    const float* Wq = (const float*)d_in[3];
    const float* bq = (const float*)d_in[4];
    const float* Wk = (const float*)d_in[5];
    const float* bk = (const float*)d_in[6];
    const float* Wv = (const float*)d_in[7];
    const float* bv = (const float*)d_in[8];
    const float* Wo = (const float*)d_in[9];
    const float* bo = (const float*)d_in[10];
    float* out = (float*)d_out;

    cudaFuncSetAttribute(fused_qkv_repack,
                         cudaFuncAttributeMaxDynamicSharedMemorySize, GEMM_SMEM);
    cudaFuncSetAttribute(gemm_o,
                         cudaFuncAttributeMaxDynamicSharedMemorySize, GEMM_SMEM);
    cudaFuncSetAttribute(attn_kernel,
                         cudaFuncAttributeMaxDynamicSharedMemorySize, ATTN_SMEM);

    prep<<<(MROWS*HD + 255) / 256, 256>>>(h, Wq, Wk, Wv, Wo);
    fused_qkv_repack<<<FUSED_BLOCKS, 256, GEMM_SMEM>>>(bq, bk, bv, ab, mk);
    attn_kernel<<<dim3(SQ / 128, BHCOUNT), 256, ATTN_SMEM>>>();
    gemm_o<<<dim3(HD / 128, MROWS / 128), 256, GEMM_SMEM>>>(bo, out);
}

// round 14
// speedup vs baseline: 1.1072x; 1.0621x over previous
#include <cuda_runtime.h>
#include <cstdint>

// Problem constants
#define SQ 1024
#define HD 768
#define NH 12
#define DH 64
#define NB 8
#define BHCOUNT (NB*NH)   // 96
#define MROWS (NB*SQ)     // 8192

// Scratch (device globals; tf32 bit patterns stored as float)
__device__ float g_q[BHCOUNT*SQ*DH];    // natural head-major tf32, pre-scaled by 0.125
__device__ float g_k[BHCOUNT*SQ*DH];    // natural head-major tf32
__device__ float g_v[BHCOUNT*SQ*DH];    // natural head-major tf32
__device__ float g_ao[MROWS*HD];        // kperm'd tf32 (for O-proj A-path)
__device__ float g_ht[MROWS*HD];        // kperm'd tf32 input h
__device__ float g_wt4[4*HD*HD];        // tf32 weights (natural)
__device__ float g_bm[(size_t)BHCOUNT*SQ*SQ];  // (bias-16)*log2e, FINF if masked; col-permuted

#define LOG2E 1.4426950408889634f
#define MASKED_ARG (-23.08312065422341f)   // (1e-14 - 16) * log2e

// ---------------------------------------------------------------------------
// helpers
// ---------------------------------------------------------------------------
__device__ __forceinline__ uint32_t f2tf(float x) {
    uint32_t r;
    asm("cvt.rna.tf32.f32 %0, %1;" : "=r"(r) : "f"(x));
    return r;
}
__device__ __forceinline__ float f2tff(float x) { return __uint_as_float(f2tf(x)); }
__device__ __forceinline__ float ex2f(float x) {
    float r;
    asm("ex2.approx.ftz.f32 %0, %1;" : "=f"(r) : "f"(x));
    return r;
}
__device__ __forceinline__ int slotf(int c) { return 2*(c&3) + ((c&4)>>2); }

__device__ __forceinline__ void mma8(float* c,
                                     uint32_t a0, uint32_t a1, uint32_t a2, uint32_t a3,
                                     uint32_t b0, uint32_t b1) {
    asm volatile(
        "mma.sync.aligned.m16n8k8.row.col.f32.tf32.tf32.f32 "
        "{%0,%1,%2,%3}, {%4,%5,%6,%7}, {%8,%9}, {%0,%1,%2,%3};"
        : "+f"(c[0]), "+f"(c[1]), "+f"(c[2]), "+f"(c[3])
        : "r"(a0), "r"(a1), "r"(a2), "r"(a3), "r"(b0), "r"(b1));
}

__device__ __forceinline__ uint32_t smem_u32(const void* p) {
    uint32_t a;
    asm("{ .reg .u64 t; cvta.to.shared.u64 t, %1; cvt.u32.u64 %0, t; }"
        : "=r"(a) : "l"(p));
    return a;
}
__device__ __forceinline__ void cpa16(uint32_t dst, const void* src) {
    asm volatile("cp.async.cg.shared.global [%0], [%1], 16;" :: "r"(dst), "l"(src));
}
#define CP_COMMIT() asm volatile("cp.async.commit_group;" ::: "memory")
#define CP_WAIT0()  asm volatile("cp.async.wait_group 0;" ::: "memory")
#define CP_WAIT1()  asm volatile("cp.async.wait_group 1;" ::: "memory")

// ---------------------------------------------------------------------------
// prep: g_ht = kperm'd tf32(h); g_wt4 = tf32(weights). float4 vectorized.
// ---------------------------------------------------------------------------
__global__ void prep(const float* __restrict__ h,
                     const float* __restrict__ wq, const float* __restrict__ wk,
                     const float* __restrict__ wv, const float* __restrict__ wo)
{
    int i4 = (blockIdx.x * 256 + threadIdx.x) * 4;
    if (i4 < MROWS*HD) {
        float4 v = *(const float4*)&h[i4];
        int k = i4 & 7;         // 0 or 4
        int base = i4 - k;
        g_ht[base + slotf(k + 0)] = f2tff(v.x);
        g_ht[base + slotf(k + 1)] = f2tff(v.y);
        g_ht[base + slotf(k + 2)] = f2tff(v.z);
        g_ht[base + slotf(k + 3)] = f2tff(v.w);
    }
    if (i4 < 4*HD*HD) {
        int z = i4 / (HD*HD), r = i4 - z*(HD*HD);
        const float* w = (z == 0) ? wq : (z == 1 ? wk : (z == 2 ? wv : wo));
        float4 v = *(const float4*)&w[r];
        v.x = f2tff(v.x); v.y = f2tff(v.y); v.z = f2tff(v.z); v.w = f2tff(v.w);
        *(float4*)&g_wt4[i4] = v;
    }
}

// ---------------------------------------------------------------------------
// GEMM tile body (tf32 mma.sync, cp.async 3-stage). Unchanged (R13).
// ---------------------------------------------------------------------------
#define GA 40
#define GB 132
#define A_ST (128*GA)
#define B_ST (32*GB)
#define STAGE (A_ST + B_ST)
#define NCHUNK (HD/32)
#define NSTAGE 3
#define GEMM_SMEM (NSTAGE*STAGE*4)   // 112128 bytes

__device__ __forceinline__ void gemm_tile(
    float* sm, int bx, int by, int z, int mode,
    const float* __restrict__ bias, float* __restrict__ Cout)
{
    const uint32_t sb = smem_u32(sm);
    const int tid = threadIdx.x;
    const int lane = tid & 31;
    const int wm = (tid >> 5) >> 2, wn = (tid >> 5) & 3;
    const int g = lane >> 2, t = lane & 3;

    const float* A = (mode == 0) ? g_ao : g_ht;
    const float* W = g_wt4 + (size_t)((mode == 0) ? 3 : z) * HD * HD;
    float* C = (mode == 0) ? Cout : (z == 0 ? g_q : (z == 1 ? g_k : g_v));
    const float qs = (mode == 1 && z == 0) ? 0.125f : 1.0f;

    const int m0 = by * 128;
    const int n0 = bx * 128;

    float acc[4][4][4];
#pragma unroll
    for (int i = 0; i < 4; ++i)
#pragma unroll
        for (int j = 0; j < 4; ++j)
#pragma unroll
            for (int r = 0; r < 4; ++r) acc[i][j][r] = 0.0f;

#define G_LOAD(cc, st) do { \
    int k0 = (cc) * 32; \
    uint32_t abase = sb + (uint32_t)((st) * STAGE) * 4; \
    uint32_t bbase = abase + A_ST * 4; \
    _Pragma("unroll") \
    for (int it = 0; it < 4; ++it) { \
        int idx = tid + it * 256; \
        int ar = idx >> 3, ac = idx & 7; \
        cpa16(abase + (uint32_t)(ar * GA + ac * 4) * 4, \
              A + (size_t)(m0 + ar) * HD + k0 + ac * 4); \
        int br = idx >> 5, bc = idx & 31; \
        int sr = (br & ~7) | slotf(br & 7); \
        cpa16(bbase + (uint32_t)(sr * GB + bc * 4) * 4, \
              W + (size_t)(k0 + br) * HD + n0 + bc * 4); \
    } \
    CP_COMMIT(); \
} while (0)

    G_LOAD(0, 0);
    G_LOAD(1, 1);

    int st = 0;
    for (int c = 0; c < NCHUNK; ++c) {
        CP_WAIT1();
        __syncthreads();
        if (c + 2 < NCHUNK) {
            int st2 = st + 2; if (st2 >= NSTAGE) st2 -= NSTAGE;
            G_LOAD(c + 2, st2);
        }

        const float* As = sm + st * STAGE;
        const float* Bs = As + A_ST;
#pragma unroll
        for (int ks = 0; ks < 4; ++ks) {
            float2 ap[4][2];
#pragma unroll
            for (int mf = 0; mf < 4; ++mf) {
                const float* p = As + (wm * 64 + mf * 16 + g) * GA + ks * 8 + 2 * t;
                ap[mf][0] = *(const float2*)p;
                ap[mf][1] = *(const float2*)(p + 8 * GA);
            }
            float bf[4][2];
#pragma unroll
            for (int nf = 0; nf < 4; ++nf) {
                const float* p = Bs + (ks * 8 + 2 * t) * GB + wn * 32 + nf * 8 + g;
                bf[nf][0] = p[0];
                bf[nf][1] = p[GB];
            }
#pragma unroll
            for (int mf = 0; mf < 4; ++mf)
#pragma unroll
                for (int nf = 0; nf < 4; ++nf)
                    mma8(acc[mf][nf],
                         __float_as_uint(ap[mf][0].x), __float_as_uint(ap[mf][1].x),
                         __float_as_uint(ap[mf][0].y), __float_as_uint(ap[mf][1].y),
                         __float_as_uint(bf[nf][0]), __float_as_uint(bf[nf][1]));
        }
        if (++st >= NSTAGE) st = 0;
    }

    // epilogue
#pragma unroll
    for (int mf = 0; mf < 4; ++mf) {
#pragma unroll
        for (int nf = 0; nf < 4; ++nf) {
            int r0 = m0 + wm * 64 + mf * 16 + g;
            int ncol0 = n0 + wn * 32 + nf * 8 + 2 * t;
            float bb0 = bias[ncol0], bb1 = bias[ncol0 + 1];
            float v00 = acc[mf][nf][0] + bb0, v01 = acc[mf][nf][1] + bb1;
            float v10 = acc[mf][nf][2] + bb0, v11 = acc[mf][nf][3] + bb1;
            if (mode == 0) {
                *(float2*)&C[(size_t)r0 * HD + ncol0] = make_float2(v00, v01);
                *(float2*)&C[(size_t)(r0 + 8) * HD + ncol0] = make_float2(v10, v11);
            } else {
                int b = r0 >> 10, sidx = r0 & 1023;
                int hh = ncol0 >> 6, dd = ncol0 & 63;
                size_t base = ((size_t)(b * NH + hh) * SQ + sidx) * DH + dd;
                *(float2*)&C[base] = make_float2(f2tff(v00 * qs), f2tff(v01 * qs));
                *(float2*)&C[base + 8 * DH] = make_float2(f2tff(v10 * qs), f2tff(v11 * qs));
            }
        }
    }
}

// ---------------------------------------------------------------------------
// repack block body (streaming hints). Unchanged (R13).
// ---------------------------------------------------------------------------
__device__ __forceinline__ void repack_block(
    float* sm, int q, int b,
    const float* __restrict__ bias, const int* __restrict__ mask)
{
    float* sbias = sm;                       // SQ*NH floats (48 KB)
    int*   smask = (int*)(sm + SQ * NH);     // SQ ints (4 KB)
    const int tid = threadIdx.x;
    const float FINF = __int_as_float(0x7f800000);

    const float* bsrc = bias + ((size_t)(b * SQ + q) * SQ) * NH;
#pragma unroll
    for (int it = 0; it < 12; ++it) {
        int i4 = (tid + it * 256) * 4;
        *(float4*)&sbias[i4] = __ldcs((const float4*)&bsrc[i4]);
    }
    {
        const int* msrc = mask + (size_t)(b * SQ + q) * SQ;
        int i4 = tid * 4;
        *(int4*)&smask[i4] = __ldcs((const int4*)&msrc[i4]);
    }
    __syncthreads();

#pragma unroll
    for (int h = 0; h < NH; ++h) {
        float* dst = g_bm + (((size_t)(b * NH + h) * SQ + q) * SQ);
        int p0 = tid * 4;
        float o[4];
#pragma unroll
        for (int e = 0; e < 4; ++e) {
            int p = p0 + e;
            int w = p & 63, t = w >> 4, idx = w & 15;
            int k = (p & ~63) + (idx >> 1) * 8 + 2 * t + (idx & 1);
            o[e] = smask[k] ? FINF : (sbias[k * NH + h] - 16.0f) * LOG2E;
        }
        __stcs((float4*)&dst[p0], make_float4(o[0], o[1], o[2], o[3]));
    }
}

// ---------------------------------------------------------------------------
// Fused dispatch: 9344 blocks, 1:8 gemm:repack interleave. Unchanged (R13).
// ---------------------------------------------------------------------------
#define FUSED_BLOCKS (9216 + 128)   // 9344

__global__ __launch_bounds__(256, 2) void fused_qkv_repack(
    const float* __restrict__ bq, const float* __restrict__ bk,
    const float* __restrict__ bv,
    const float* __restrict__ bias, const int* __restrict__ mask)
{
    extern __shared__ float sm[];
    const int gid = blockIdx.x;
    if (((gid & 7) == 0) && (gid < 9216)) {
        int gb = gid >> 3;               // 0..1151
        int z = gb / 384;
        int rem = gb - z * 384;
        int by = rem / 6, bx = rem - by * 6;
        const float* bias_z = (z == 0) ? bq : (z == 1 ? bk : bv);
        gemm_tile(sm, bx, by, z, 1, bias_z, nullptr);
    } else {
        int rix = (gid < 9216) ? (gid - (gid >> 3) - 1) : (gid - 1152);
        int q = rix & 1023, b = rix >> 10;
        repack_block(sm, q, b, bias, mask);
    }
}

// ---------------------------------------------------------------------------
// O-projection GEMM kernel
// ---------------------------------------------------------------------------
__global__ __launch_bounds__(256, 2) void gemm_o(
    const float* __restrict__ bo, float* __restrict__ Cout)
{
    extern __shared__ float sm[];
    gemm_tile(sm, blockIdx.x, blockIdx.y, 0, 0, bo, Cout);
}

// ---------------------------------------------------------------------------
// Flash attention — bm now cp.async-prefetched one chunk ahead into the Ps
// region (warp-private rows: bm staging, P, and PV all touch only rows
// [16w, 16w+16), so program order + syncwarp is sufficient).
// Group order per chunk: A(KV), B(bm). wait_group 1 before S-mma (KV ready),
// wait_group 1 before fold (bm ready).
// smem floats: K[2][64][68], V[2][64][72], Ps[128][68] (Q stage / bm / P).
// ---------------------------------------------------------------------------
#define KSTR 68
#define VSTR 72
#define K_OFF(s)  ((s)*64*KSTR)
#define V_OFF(s)  (2*64*KSTR + (s)*64*VSTR)
#define P_OFF     (2*64*KSTR + 2*64*VSTR)
#define ATTN_FLOATS (P_OFF + 128*KSTR)
#define ATTN_SMEM (ATTN_FLOATS*4)   // 106496 bytes

__global__ __launch_bounds__(256, 2) void attn_kernel()
{
    extern __shared__ float sm[];
    const uint32_t sb = smem_u32(sm);
    const float FINF = __int_as_float(0x7f800000);
    float* Ps = sm + P_OFF;

    const int bh = blockIdx.y;
    const int b = bh / NH, hh = bh - b * NH;
    const int q0 = blockIdx.x * 128;
    const int tid = threadIdx.x;
    const int wid = tid >> 5, lane = tid & 31;
    const int g = lane >> 2, t = lane & 3;
    const int rl = wid * 16 + g;

    const float* qg = g_q + ((size_t)bh * SQ + q0) * DH;
    const float* kg = g_k + (size_t)bh * SQ * DH;
    const float* vg = g_v + (size_t)bh * SQ * DH;
    // bm rows for this warp (16 rows starting at q0 + wid*16)
    const float* bmw = g_bm + ((size_t)bh * SQ + q0 + wid * 16) * SQ;

    // ---- bm chunk staging: each warp copies its own 16 rows x 64 cols ----
#define BM_LOAD(kk) do { \
    int kc0 = (kk) * 64; \
    _Pragma("unroll") \
    for (int i = 0; i < 8; ++i) { \
        int idx = lane + i * 32; \
        int row = idx >> 4, seg = idx & 15; \
        cpa16(sb + (uint32_t)(P_OFF + (wid * 16 + row) * KSTR + seg * 4) * 4, \
              bmw + (size_t)row * SQ + kc0 + seg * 4); \
    } \
    CP_COMMIT(); \
} while (0)

    // prologue: KV(0) group, Q stage + extract, then bm(0) group
#pragma unroll
    for (int it = 0; it < 4; ++it) {
        int idx = tid + it * 256;
        int row = idx >> 4, c4 = idx & 15;
        cpa16(sb + (uint32_t)(K_OFF(0) + row * KSTR + c4 * 4) * 4,
              kg + (size_t)row * 64 + c4 * 4);
        cpa16(sb + (uint32_t)(V_OFF(0) + row * VSTR + c4 * 4) * 4,
              vg + (size_t)row * 64 + c4 * 4);
    }
    CP_COMMIT();   // group A0

#pragma unroll
    for (int it = 0; it < 8; ++it) {
        int idx = tid + it * 256;
        int row = idx >> 4, c4 = idx & 15;
        *(float4*)&Ps[row * KSTR + c4 * 4] = *(const float4*)&qg[(size_t)row * 64 + c4 * 4];
    }
    __syncthreads();
    uint32_t qf[8][4];
#pragma unroll
    for (int ks = 0; ks < 8; ++ks) {
        qf[ks][0] = __float_as_uint(Ps[rl * KSTR + ks * 8 + t]);
        qf[ks][1] = __float_as_uint(Ps[(rl + 8) * KSTR + ks * 8 + t]);
        qf[ks][2] = __float_as_uint(Ps[rl * KSTR + ks * 8 + t + 4]);
        qf[ks][3] = __float_as_uint(Ps[(rl + 8) * KSTR + ks * 8 + t + 4]);
    }
    __syncthreads();   // Ps free
    BM_LOAD(0);        // group B0

    float l0 = 0.0f, l1 = 0.0f;
    float oacc[8][4];
#pragma unroll
    for (int nf = 0; nf < 8; ++nf)
#pragma unroll
        for (int r = 0; r < 4; ++r) oacc[nf][r] = 0.0f;

    for (int kb = 0; kb < SQ / 64; ++kb) {
        const int s = kb & 1;

        // KV(kb) complete (B_kb may still be pending); then barrier for visibility
        CP_WAIT1();
        __syncthreads();

        // issue KV(kb+1) into buffer s^1 (that buffer's last readers finished
        // before the barrier above)
        if (kb + 1 < SQ / 64) {
            const int kn = (kb + 1) * 64;
#pragma unroll
            for (int it = 0; it < 4; ++it) {
                int idx = tid + it * 256;
                int row = idx >> 4, c4 = idx & 15;
                cpa16(sb + (uint32_t)(K_OFF(s ^ 1) + row * KSTR + c4 * 4) * 4,
                      kg + (size_t)(kn + row) * 64 + c4 * 4);
                cpa16(sb + (uint32_t)(V_OFF(s ^ 1) + row * VSTR + c4 * 4) * 4,
                      vg + (size_t)(kn + row) * 64 + c4 * 4);
            }
            CP_COMMIT();   // group A_{kb+1}
        }

        // ---- S = Q K^T (sacc = qk * 0.125, Q pre-scaled) ----
        const float* Ksf = sm + K_OFF(s);
        float sacc[8][4];
#pragma unroll
        for (int nf = 0; nf < 8; ++nf)
#pragma unroll
            for (int r = 0; r < 4; ++r) sacc[nf][r] = 0.0f;
#pragma unroll
        for (int ks = 0; ks < 8; ++ks) {
#pragma unroll
            for (int nf = 0; nf < 8; ++nf) {
                const float* kp = Ksf + (nf * 8 + g) * KSTR + ks * 8 + t;
                mma8(sacc[nf], qf[ks][0], qf[ks][1], qf[ks][2], qf[ks][3],
                     __float_as_uint(kp[0]), __float_as_uint(kp[4]));
            }
        }

        // bm(kb) complete (A_{kb+1} may still be pending)
        if (kb + 1 < SQ / 64) CP_WAIT1(); else CP_WAIT0();
        __syncwarp();

        // ---- fold: arg = sacc*log2e + bm (LDS from Ps); ex2 ----
        float rs0 = 0.0f, rs1 = 0.0f;
#pragma unroll
        for (int v = 0; v < 4; ++v) {
            float4 U = *(const float4*)&Ps[rl * KSTR + t * 16 + v * 4];
            float4 Wv4 = *(const float4*)&Ps[(rl + 8) * KSTR + t * 16 + v * 4];
            {
                int nf = 2 * v;
                float a0 = (U.x == FINF)   ? MASKED_ARG : fmaf(sacc[nf][0], LOG2E, U.x);
                float a1 = (U.y == FINF)   ? MASKED_ARG : fmaf(sacc[nf][1], LOG2E, U.y);
                float a2 = (Wv4.x == FINF) ? MASKED_ARG : fmaf(sacc[nf][2], LOG2E, Wv4.x);
                float a3 = (Wv4.y == FINF) ? MASKED_ARG : fmaf(sacc[nf][3], LOG2E, Wv4.y);
                sacc[nf][0] = ex2f(a0); sacc[nf][1] = ex2f(a1);
                sacc[nf][2] = ex2f(a2); sacc[nf][3] = ex2f(a3);
                rs0 += sacc[nf][0] + sacc[nf][1];
                rs1 += sacc[nf][2] + sacc[nf][3];
            }
            {
                int nf = 2 * v + 1;
                float a0 = (U.z == FINF)   ? MASKED_ARG : fmaf(sacc[nf][0], LOG2E, U.z);
                float a1 = (U.w == FINF)   ? MASKED_ARG : fmaf(sacc[nf][1], LOG2E, U.w);
                float a2 = (Wv4.z == FINF) ? MASKED_ARG : fmaf(sacc[nf][2], LOG2E, Wv4.z);
                float a3 = (Wv4.w == FINF) ? MASKED_ARG : fmaf(sacc[nf][3], LOG2E, Wv4.w);
                sacc[nf][0] = ex2f(a0); sacc[nf][1] = ex2f(a1);
                sacc[nf][2] = ex2f(a2); sacc[nf][3] = ex2f(a3);
                rs0 += sacc[nf][0] + sacc[nf][1];
                rs1 += sacc[nf][2] + sacc[nf][3];
            }
        }
        l0 += rs0;
        l1 += rs1;
        __syncwarp();   // all lanes' bm reads done before P overwrites Ps

        // ---- P (tf32 bits) -> smem, warp-local rows ----
#pragma unroll
        for (int nf = 0; nf < 8; ++nf) {
            int kc = nf * 8 + 2 * t;
            *(float2*)&Ps[rl * KSTR + kc] =
                make_float2(f2tff(sacc[nf][0]), f2tff(sacc[nf][1]));
            *(float2*)&Ps[(rl + 8) * KSTR + kc] =
                make_float2(f2tff(sacc[nf][2]), f2tff(sacc[nf][3]));
        }
        __syncwarp();

        // ---- O += P V ----
        const float* Vsf = sm + V_OFF(s);
#pragma unroll
        for (int ks = 0; ks < 8; ++ks) {
            const float* pp = Ps + rl * KSTR + ks * 8 + t;
            uint32_t a0 = __float_as_uint(pp[0]);
            uint32_t a1 = __float_as_uint(pp[8 * KSTR]);
            uint32_t a2 = __float_as_uint(pp[4]);
            uint32_t a3 = __float_as_uint(pp[8 * KSTR + 4]);
#pragma unroll
            for (int nf = 0; nf < 8; ++nf) {
                const float* vp = Vsf + (ks * 8 + t) * VSTR + nf * 8 + g;
                mma8(oacc[nf], a0, a1, a2, a3,
                     __float_as_uint(vp[0]), __float_as_uint(vp[4 * VSTR]));
            }
        }

        // ---- prefetch bm(kb+1) into Ps (P fully consumed by this warp) ----
        if (kb + 1 < SQ / 64) BM_LOAD(kb + 1);   // group B_{kb+1}
    }

    // ---- final l reduction (quad) + normalize + write g_ao (kperm tf32) ----
    const int r0 = q0 + rl, r1 = r0 + 8;
    l0 += __shfl_xor_sync(0xffffffffu, l0, 1);
    l0 += __shfl_xor_sync(0xffffffffu, l0, 2);
    l1 += __shfl_xor_sync(0xffffffffu, l1, 1);
    l1 += __shfl_xor_sync(0xffffffffu, l1, 2);
    float inv0 = 1.0f / l0, inv1 = 1.0f / l1;
    int s0 = slotf(2 * t), s1 = slotf(2 * t + 1);
#pragma unroll
    for (int nf = 0; nf < 8; ++nf) {
        int colbase = hh * 64 + nf * 8;
        size_t b0 = (size_t)(b * SQ + r0) * HD + colbase;
        size_t b1 = (size_t)(b * SQ + r1) * HD + colbase;
        g_ao[b0 + s0] = f2tff(oacc[nf][0] * inv0);
        g_ao[b0 + s1] = f2tff(oacc[nf][1] * inv0);
        g_ao[b1 + s0] = f2tff(oacc[nf][2] * inv1);
        g_ao[b1 + s1] = f2tff(oacc[nf][3] * inv1);
    }
}

// ---------------------------------------------------------------------------
extern "C" void kernel_launch(void* const* d_in, const int* in_sizes, int n_in,
                              void* d_out, int out_size)
{
    const float* h  = (const float*)d_in[0];
    const float* ab = (const float*)d_in[1];
    const int*   mk = (const int*)d_in[2];
    const float* Wq = (const float*)d_in[3];
    const float* bq = (const float*)d_in[4];
    const float* Wk = (const float*)d_in[5];
    const float* bk = (const float*)d_in[6];
    const float* Wv = (const float*)d_in[7];
    const float* bv = (const float*)d_in[8];
    const float* Wo = (const float*)d_in[9];
    const float* bo = (const float*)d_in[10];
    float* out = (float*)d_out;

    cudaFuncSetAttribute(fused_qkv_repack,
                         cudaFuncAttributeMaxDynamicSharedMemorySize, GEMM_SMEM);
    cudaFuncSetAttribute(gemm_o,
                         cudaFuncAttributeMaxDynamicSharedMemorySize, GEMM_SMEM);
    cudaFuncSetAttribute(attn_kernel,
                         cudaFuncAttributeMaxDynamicSharedMemorySize, ATTN_SMEM);

    prep<<<(MROWS*HD/4 + 255) / 256, 256>>>(h, Wq, Wk, Wv, Wo);
    fused_qkv_repack<<<FUSED_BLOCKS, 256, GEMM_SMEM>>>(bq, bk, bv, ab, mk);
    attn_kernel<<<dim3(SQ / 128, BHCOUNT), 256, ATTN_SMEM>>>();
    gemm_o<<<dim3(HD / 128, MROWS / 128), 256, GEMM_SMEM>>>(bo, out);
}